// round 16
// baseline (speedup 1.0000x reference)
#include <cuda_runtime.h>
#include <math.h>

#define Tn  512
#define Bn  32
#define Hn  1024
#define G4n 4096

typedef unsigned long long ull;

// ----------------------------- scratch (device globals; allocation-free) ---
__device__ float g_xgT[(size_t)Tn * G4n * Bn];   // [T][4H][B]  input projections
__device__ float g_y0 [(size_t)Tn * Bn * Hn];    // [T][B][H]   layer-0 output
__device__ float g_hT [Hn * Bn];                 // [H][B]
__device__ float g_c0 [Hn * Bn];
__device__ float g_c1 [Hn * Bn];
__device__ unsigned g_bar_count;                 // zero-initialized
__device__ unsigned g_bar_gen;

// ----------------------------- f32x2 helpers -------------------------------
__device__ __forceinline__ ull pack2(float lo, float hi) {
    ull r; asm("mov.b64 %0, {%1,%2};" : "=l"(r) : "f"(lo), "f"(hi)); return r;
}
__device__ __forceinline__ ull ffma2(ull a, ull b, ull c) {
    ull d; asm("fma.rn.f32x2 %0, %1, %2, %3;" : "=l"(d) : "l"(a), "l"(b), "l"(c));
    return d;
}
__device__ __forceinline__ float hsum2(ull a) {
    float lo, hi; asm("mov.b64 {%0,%1}, %2;" : "=f"(lo), "=f"(hi) : "l"(a));
    return lo + hi;
}

// ----------------------------- software grid barrier -----------------------
__device__ __forceinline__ void grid_barrier(unsigned nb) {
    __syncthreads();
    if (threadIdx.x == 0) {
        __threadfence();
        volatile unsigned* genp = &g_bar_gen;
        unsigned gen = *genp;
        if (atomicAdd(&g_bar_count, 1u) == nb - 1u) {
            atomicExch(&g_bar_count, 0u);
            __threadfence();
            atomicAdd(&g_bar_gen, 1u);
        } else {
            while (*genp == gen) { __nanosleep(32); }
            __threadfence();
        }
    }
    __syncthreads();
}

// ----------------------------- input projection GEMM -----------------------
// C[m][n] = sum_k A[m][k] * W[n][k],  M = T*B = 16384, N = 4096, K = 1024.
// Output written transposed into g_xgT[t][n][b] with m = t*32 + b.
// Block tile: 128 M x 64 N, k-chunk 32. Thread tile: 8 M x 4 N, f32x2 over M.
__global__ __launch_bounds__(256)
void gemm_xproj(const float* __restrict__ A, const float* __restrict__ W, int fromY0)
{
    __shared__ __align__(16) float sA[32][130];   // [k][m], stride 130 (even, low-conflict)
    __shared__ __align__(16) float sB[32][66];    // [k][n]

    const float* Ap = fromY0 ? (const float*)g_y0 : A;

    const int tid = threadIdx.x;
    const int tx  = tid & 15;            // n-group: 4 n each
    const int ty  = tid >> 4;            // m-group: 8 m each
    const int mbase = blockIdx.x * 128;
    const int nbase = blockIdx.y * 64;

    ull acc[4][4];
    #pragma unroll
    for (int i = 0; i < 4; i++)
        #pragma unroll
        for (int j = 0; j < 4; j++) acc[i][j] = 0ull;

    for (int kc = 0; kc < Hn; kc += 32) {
        __syncthreads();
        // stage A tile: 128 m x 32 k (coalesced float4 over k)
        for (int i = tid; i < 128 * 8; i += 256) {
            int m = i >> 3, k4 = (i & 7) * 4;
            float4 v = *reinterpret_cast<const float4*>(Ap + (size_t)(mbase + m) * Hn + kc + k4);
            sA[k4 + 0][m] = v.x; sA[k4 + 1][m] = v.y;
            sA[k4 + 2][m] = v.z; sA[k4 + 3][m] = v.w;
        }
        // stage B tile: 64 n x 32 k
        for (int i = tid; i < 64 * 8; i += 256) {
            int n = i >> 3, k4 = (i & 7) * 4;
            float4 v = *reinterpret_cast<const float4*>(W + (size_t)(nbase + n) * Hn + kc + k4);
            sB[k4 + 0][n] = v.x; sB[k4 + 1][n] = v.y;
            sB[k4 + 2][n] = v.z; sB[k4 + 3][n] = v.w;
        }
        __syncthreads();
        #pragma unroll
        for (int kk = 0; kk < 32; kk++) {
            ull am[4];
            #pragma unroll
            for (int i = 0; i < 4; i++)
                am[i] = *reinterpret_cast<const ull*>(&sA[kk][ty * 8 + i * 2]);
            #pragma unroll
            for (int j = 0; j < 4; j++) {
                float bv = sB[kk][tx * 4 + j];
                ull b2 = pack2(bv, bv);
                #pragma unroll
                for (int i = 0; i < 4; i++)
                    acc[i][j] = ffma2(am[i], b2, acc[i][j]);
            }
        }
    }
    #pragma unroll
    for (int i = 0; i < 4; i++) {
        #pragma unroll
        for (int j = 0; j < 4; j++) {
            float lo, hi;
            asm("mov.b64 {%0,%1}, %2;" : "=f"(lo), "=f"(hi) : "l"(acc[i][j]));
            int m0 = mbase + ty * 8 + i * 2;
            int n  = nbase + tx * 4 + j;
            g_xgT[((size_t)(m0 >> 5) * G4n + n) * Bn + (m0 & 31)] = lo;
            int m1 = m0 + 1;
            g_xgT[((size_t)(m1 >> 5) * G4n + n) * Bn + (m1 & 31)] = hi;
        }
    }
}

// ----------------------------- state init / final-state copy ---------------
__global__ void zero_state() {
    int i = blockIdx.x * blockDim.x + threadIdx.x;
    if (i < Hn * Bn) { g_hT[i] = 0.f; g_c0[i] = 0.f; }
}

__global__ void copy_state(float* __restrict__ out, int layer) {
    int i = blockIdx.x * blockDim.x + threadIdx.x;   // 0..32767
    if (i < Hn * Bn) {
        int j = i >> 5, b = i & 31;
        size_t ybase = (size_t)Tn * Bn * Hn;
        // hn[layer][b][j], cn[layer][b][j]; final c lives in g_c0 (T even)
        out[ybase + (size_t)layer * Bn * Hn + (size_t)b * Hn + j] = g_hT[i];
        out[ybase + (size_t)2 * Bn * Hn + (size_t)layer * Bn * Hn + (size_t)b * Hn + j] = g_c0[i];
    }
}

// ----------------------------- persistent recurrent kernel -----------------
// 128 CTAs x 256 threads, 1 CTA/SM (224KB dyn smem guarantees it; 128 <= 148 SMs).
// CTA r owns columns j = r*8 .. r*8+7. Warp wp covers k in [wp*128, wp*128+128).
// Weights (Whh rows i/f/g/o + Wpi + Wpf for the 8 owned columns) staged in smem once.
__global__ __launch_bounds__(256, 1)
void lstm_layer(const float* __restrict__ Whh, const float* __restrict__ Wpi,
                const float* __restrict__ Wpf, const float* __restrict__ Wpo,
                float* __restrict__ yOut, int isLayer1)
{
    extern __shared__ __align__(16) float smem[];
    float* sw   = smem;                  // [6][8][1024] = 196608 B
    float* accb = smem + 6 * 8 * 1024;   // [8 warps][8 cols][4 gates][32] = 32768 B

    const int r     = blockIdx.x;
    const int tid   = threadIdx.x;
    const int lane  = tid & 31;
    const int wp    = tid >> 5;
    const int kbase = wp * 128;
    const int jown  = r * 8 + wp;        // column this warp finalizes

    // ---- stage step-invariant weights into smem (once) ----
    for (int idx = tid; idx < 8 * Hn; idx += 256) {
        int lc = idx >> 10, k = idx & (Hn - 1);
        int j = r * 8 + lc;
        sw[(0 * 8 + lc) * Hn + k] = Whh[(size_t)j * Hn + k];
        sw[(1 * 8 + lc) * Hn + k] = Whh[(size_t)(Hn + j) * Hn + k];
        sw[(2 * 8 + lc) * Hn + k] = Whh[(size_t)(2 * Hn + j) * Hn + k];
        sw[(3 * 8 + lc) * Hn + k] = Whh[(size_t)(3 * Hn + j) * Hn + k];
        sw[(4 * 8 + lc) * Hn + k] = Wpi[(size_t)j * Hn + k];
        sw[(5 * 8 + lc) * Hn + k] = Wpf[(size_t)j * Hn + k];
    }
    __syncthreads();

    float cn_reg = 0.f, opart = 0.f;

    for (int t = 0; t < Tn; t++) {
        const float* cread  = (t & 1) ? g_c1 : g_c0;
        float*       cwrite = (t & 1) ? g_c0 : g_c1;
        const float* xg = g_xgT + (size_t)t * G4n * Bn;

        // ===== phase 1: partial dots for i, f, g, o over this warp's k-slice =====
        ull ai[8], af[8], ag[8], ao[8];
        #pragma unroll
        for (int lc = 0; lc < 8; lc++) { ai[lc] = 0; af[lc] = 0; ag[lc] = 0; ao[lc] = 0; }

        for (int cc = 0; cc < 8; cc++) {
            const int k0 = kbase + cc * 16;
            ull sh2[8], sc2[8];
            #pragma unroll
            for (int u = 0; u < 8; u++) {
                float h0 = __ldcg(&g_hT [(k0 + 2 * u)     * Bn + lane]);
                float h1 = __ldcg(&g_hT [(k0 + 2 * u + 1) * Bn + lane]);
                sh2[u] = pack2(h0, h1);
                float c0v = __ldcg(&cread[(k0 + 2 * u)     * Bn + lane]);
                float c1v = __ldcg(&cread[(k0 + 2 * u + 1) * Bn + lane]);
                sc2[u] = pack2(c0v, c1v);
            }
            #pragma unroll
            for (int lc = 0; lc < 8; lc++) {
                const ulonglong2* pwi = reinterpret_cast<const ulonglong2*>(sw + (0 * 8 + lc) * Hn + k0);
                const ulonglong2* pwf = reinterpret_cast<const ulonglong2*>(sw + (1 * 8 + lc) * Hn + k0);
                const ulonglong2* pwg = reinterpret_cast<const ulonglong2*>(sw + (2 * 8 + lc) * Hn + k0);
                const ulonglong2* pwo = reinterpret_cast<const ulonglong2*>(sw + (3 * 8 + lc) * Hn + k0);
                const ulonglong2* ppi = reinterpret_cast<const ulonglong2*>(sw + (4 * 8 + lc) * Hn + k0);
                const ulonglong2* ppf = reinterpret_cast<const ulonglong2*>(sw + (5 * 8 + lc) * Hn + k0);
                #pragma unroll
                for (int u = 0; u < 4; u++) {
                    ulonglong2 wi = pwi[u], wf = pwf[u], wg = pwg[u], wo = pwo[u];
                    ulonglong2 vi = ppi[u], vf = ppf[u];
                    ai[lc] = ffma2(wi.x, sh2[2 * u],     ai[lc]);
                    ai[lc] = ffma2(wi.y, sh2[2 * u + 1], ai[lc]);
                    ai[lc] = ffma2(vi.x, sc2[2 * u],     ai[lc]);
                    ai[lc] = ffma2(vi.y, sc2[2 * u + 1], ai[lc]);
                    af[lc] = ffma2(wf.x, sh2[2 * u],     af[lc]);
                    af[lc] = ffma2(wf.y, sh2[2 * u + 1], af[lc]);
                    af[lc] = ffma2(vf.x, sc2[2 * u],     af[lc]);
                    af[lc] = ffma2(vf.y, sc2[2 * u + 1], af[lc]);
                    ag[lc] = ffma2(wg.x, sh2[2 * u],     ag[lc]);
                    ag[lc] = ffma2(wg.y, sh2[2 * u + 1], ag[lc]);
                    ao[lc] = ffma2(wo.x, sh2[2 * u],     ao[lc]);
                    ao[lc] = ffma2(wo.y, sh2[2 * u + 1], ao[lc]);
                }
            }
        }
        #pragma unroll
        for (int lc = 0; lc < 8; lc++) {
            accb[((wp * 8 + lc) * 4 + 0) * 32 + lane] = hsum2(ai[lc]);
            accb[((wp * 8 + lc) * 4 + 1) * 32 + lane] = hsum2(af[lc]);
            accb[((wp * 8 + lc) * 4 + 2) * 32 + lane] = hsum2(ag[lc]);
            accb[((wp * 8 + lc) * 4 + 3) * 32 + lane] = hsum2(ao[lc]);
        }
        __syncthreads();

        // warp wp reduces its own column jown across the 8 warps' partials
        {
            float si = 0.f, sf = 0.f, sg = 0.f, so = 0.f;
            #pragma unroll
            for (int w = 0; w < 8; w++) {
                si += accb[((w * 8 + wp) * 4 + 0) * 32 + lane];
                sf += accb[((w * 8 + wp) * 4 + 1) * 32 + lane];
                sg += accb[((w * 8 + wp) * 4 + 2) * 32 + lane];
                so += accb[((w * 8 + wp) * 4 + 3) * 32 + lane];
            }
            const size_t xb = (size_t)jown * Bn + lane;
            si += xg[xb];
            sf += xg[(size_t)Hn * Bn + xb];
            sg += xg[(size_t)2 * Hn * Bn + xb];
            so += xg[(size_t)3 * Hn * Bn + xb];
            float cold = __ldcg(&cread[jown * Bn + lane]);
            float ig = 1.f / (1.f + __expf(-si));
            float fg = 1.f / (1.f + __expf(-sf));
            float gg = tanhf(sg);
            cn_reg = fg * cold + ig * gg;
            opart  = so;                               // NO sigmoid on o (per reference)
            __stcg(&cwrite[jown * Bn + lane], cn_reg);
        }
        grid_barrier(gridDim.x);

        // ===== phase 2: o peephole  (o += c_new @ Wpo^T), then h_new =====
        ull aco[8];
        #pragma unroll
        for (int lc = 0; lc < 8; lc++) aco[lc] = 0;
        for (int cc = 0; cc < 8; cc++) {
            const int k0 = kbase + cc * 16;
            ull sc2[8];
            #pragma unroll
            for (int u = 0; u < 8; u++) {
                float c0v = __ldcg(&cwrite[(k0 + 2 * u)     * Bn + lane]);
                float c1v = __ldcg(&cwrite[(k0 + 2 * u + 1) * Bn + lane]);
                sc2[u] = pack2(c0v, c1v);
            }
            #pragma unroll
            for (int lc = 0; lc < 8; lc++) {
                const int j = r * 8 + lc;
                const ulonglong2* pw = reinterpret_cast<const ulonglong2*>(Wpo + (size_t)j * Hn + k0);
                #pragma unroll
                for (int u = 0; u < 4; u++) {
                    ulonglong2 w = pw[u];
                    aco[lc] = ffma2(w.x, sc2[2 * u],     aco[lc]);
                    aco[lc] = ffma2(w.y, sc2[2 * u + 1], aco[lc]);
                }
            }
        }
        #pragma unroll
        for (int lc = 0; lc < 8; lc++)
            accb[((wp * 8 + lc) * 4 + 0) * 32 + lane] = hsum2(aco[lc]);
        __syncthreads();
        {
            float so = opart;
            #pragma unroll
            for (int w = 0; w < 8; w++)
                so += accb[((w * 8 + wp) * 4 + 0) * 32 + lane];
            float hnew = so * tanhf(cn_reg);
            __stcg(&g_hT[jown * Bn + lane], hnew);
            if (isLayer1)
                yOut[((size_t)t * Bn + lane) * Hn + jown] = hnew;
            else
                g_y0[((size_t)t * Bn + lane) * Hn + jown] = hnew;
        }
        grid_barrier(gridDim.x);
    }
}

// ----------------------------- launch --------------------------------------
extern "C" void kernel_launch(void* const* d_in, const int* in_sizes, int n_in,
                              void* d_out, int out_size) {
    (void)in_sizes; (void)n_in; (void)out_size;
    const float* x    = (const float*)d_in[0];
    const float* wih0 = (const float*)d_in[1];
    const float* whh0 = (const float*)d_in[2];
    const float* wpi0 = (const float*)d_in[3];
    const float* wpf0 = (const float*)d_in[4];
    const float* wpo0 = (const float*)d_in[5];
    const float* wih1 = (const float*)d_in[6];
    const float* whh1 = (const float*)d_in[7];
    const float* wpi1 = (const float*)d_in[8];
    const float* wpf1 = (const float*)d_in[9];
    const float* wpo1 = (const float*)d_in[10];
    float* out = (float*)d_out;

    static const int LSTM_SMEM = (6 * 8 * 1024 + 8 * 8 * 4 * 32) * 4;  // 229376 B
    cudaFuncSetAttribute(lstm_layer, cudaFuncAttributeMaxDynamicSharedMemorySize, LSTM_SMEM);

    dim3 gg(Tn * Bn / 128, G4n / 64);   // (128, 64)

    // layer 0
    gemm_xproj<<<gg, 256>>>(x, wih0, 0);
    zero_state<<<128, 256>>>();
    lstm_layer<<<128, 256, LSTM_SMEM>>>(whh0, wpi0, wpf0, wpo0, out, 0);
    copy_state<<<128, 256>>>(out, 0);

    // layer 1
    gemm_xproj<<<gg, 256>>>(nullptr, wih1, 1);
    zero_state<<<128, 256>>>();
    lstm_layer<<<128, 256, LSTM_SMEM>>>(whh1, wpi1, wpf1, wpo1, out, 1);
    copy_state<<<128, 256>>>(out, 1);
}

// round 17
// speedup vs baseline: 1.1817x; 1.1817x over previous
#include <cuda_runtime.h>
#include <math.h>

#define Tn   512
#define Bn   32
#define Hn   1024
#define G4n  4096
#define NCTA 148
#define NC   7          // max columns per CTA

typedef unsigned long long ull;

// ----------------------------- scratch (device globals; allocation-free) ---
__device__ float g_xgT[(size_t)Tn * G4n * Bn];   // [T][4H][B]
__device__ float g_y0T[(size_t)Tn * Hn * Bn];    // [T][H][B]  layer-0 output (transposed)
__device__ float g_y1T[(size_t)Tn * Hn * Bn];    // [T][H][B]  layer-1 output (transposed)
__device__ float g_hT [Hn * Bn];                 // [H][B]
__device__ float g_c0 [Hn * Bn];
__device__ float g_c1 [Hn * Bn];
__device__ __align__(128) unsigned g_bar_count;  // own 128B line
__device__ __align__(128) unsigned g_bar_gen;    // own 128B line

// ----------------------------- f32x2 helpers -------------------------------
__device__ __forceinline__ ull pack2(float lo, float hi) {
    ull r; asm("mov.b64 %0, {%1,%2};" : "=l"(r) : "f"(lo), "f"(hi)); return r;
}
__device__ __forceinline__ ull ffma2(ull a, ull b, ull c) {
    ull d; asm("fma.rn.f32x2 %0, %1, %2, %3;" : "=l"(d) : "l"(a), "l"(b), "l"(c));
    return d;
}
__device__ __forceinline__ float hsum2(ull a) {
    float lo, hi; asm("mov.b64 {%0,%1}, %2;" : "=f"(lo), "=f"(hi) : "l"(a));
    return lo + hi;
}

// ----------------------------- software grid barrier -----------------------
__device__ __forceinline__ void grid_barrier(unsigned nb) {
    __syncthreads();
    if (threadIdx.x == 0) {
        __threadfence();
        volatile unsigned* genp = &g_bar_gen;
        unsigned gen = *genp;
        if (atomicAdd(&g_bar_count, 1u) == nb - 1u) {
            atomicExch(&g_bar_count, 0u);
            __threadfence();
            atomicAdd(&g_bar_gen, 1u);
        } else {
            while (*genp == gen) { __nanosleep(128); }
            __threadfence();
        }
    }
    __syncthreads();
}

// ----------------------------- input projection GEMM -----------------------
// C[m][n] = sum_k A[m][k] * W[n][k],  M = 16384, N = 4096, K = 1024.
// Output transposed into g_xgT[t][n][b], m = t*32 + b.
// fromY0: A is g_y0T with layout [T][K][B].
__global__ __launch_bounds__(256)
void gemm_xproj(const float* __restrict__ A, const float* __restrict__ W, int fromY0)
{
    __shared__ __align__(16) float sA[32][130];
    __shared__ __align__(16) float sB[32][66];

    const int tid = threadIdx.x;
    const int tx  = tid & 15;
    const int ty  = tid >> 4;
    const int mbase = blockIdx.x * 128;
    const int nbase = blockIdx.y * 64;
    const int t0    = mbase >> 5;        // 4 consecutive t values per tile

    ull acc[4][4];
    #pragma unroll
    for (int i = 0; i < 4; i++)
        #pragma unroll
        for (int j = 0; j < 4; j++) acc[i][j] = 0ull;

    for (int kc = 0; kc < Hn; kc += 32) {
        __syncthreads();
        if (fromY0) {
            // A[m][k] = g_y0T[(t*H + k)*B + b],  m = t*32+b  (coalesced over b)
            for (int i = tid; i < 128 * 32; i += 256) {
                int tl = i >> 10, k = (i >> 5) & 31, b = i & 31;
                sA[k][tl * 32 + b] =
                    g_y0T[((size_t)(t0 + tl) * Hn + kc + k) * Bn + b];
            }
        } else {
            for (int i = tid; i < 128 * 8; i += 256) {
                int m = i >> 3, k4 = (i & 7) * 4;
                float4 v = *reinterpret_cast<const float4*>(
                    A + (size_t)(mbase + m) * Hn + kc + k4);
                sA[k4 + 0][m] = v.x; sA[k4 + 1][m] = v.y;
                sA[k4 + 2][m] = v.z; sA[k4 + 3][m] = v.w;
            }
        }
        for (int i = tid; i < 64 * 8; i += 256) {
            int n = i >> 3, k4 = (i & 7) * 4;
            float4 v = *reinterpret_cast<const float4*>(
                W + (size_t)(nbase + n) * Hn + kc + k4);
            sB[k4 + 0][n] = v.x; sB[k4 + 1][n] = v.y;
            sB[k4 + 2][n] = v.z; sB[k4 + 3][n] = v.w;
        }
        __syncthreads();
        #pragma unroll
        for (int kk = 0; kk < 32; kk++) {
            ull am[4];
            #pragma unroll
            for (int i = 0; i < 4; i++)
                am[i] = *reinterpret_cast<const ull*>(&sA[kk][ty * 8 + i * 2]);
            #pragma unroll
            for (int j = 0; j < 4; j++) {
                float bv = sB[kk][tx * 4 + j];
                ull b2 = pack2(bv, bv);
                #pragma unroll
                for (int i = 0; i < 4; i++)
                    acc[i][j] = ffma2(am[i], b2, acc[i][j]);
            }
        }
    }
    #pragma unroll
    for (int i = 0; i < 4; i++) {
        #pragma unroll
        for (int j = 0; j < 4; j++) {
            float lo, hi;
            asm("mov.b64 {%0,%1}, %2;" : "=f"(lo), "=f"(hi) : "l"(acc[i][j]));
            int m0 = mbase + ty * 8 + i * 2;
            int n  = nbase + tx * 4 + j;
            g_xgT[((size_t)(m0 >> 5) * G4n + n) * Bn + (m0 & 31)] = lo;
            int m1 = m0 + 1;
            g_xgT[((size_t)(m1 >> 5) * G4n + n) * Bn + (m1 & 31)] = hi;
        }
    }
}

// ----------------------------- state init / final-state copy ---------------
__global__ void zero_state() {
    int i = blockIdx.x * blockDim.x + threadIdx.x;
    if (i < Hn * Bn) { g_hT[i] = 0.f; g_c0[i] = 0.f; }
}

__global__ void copy_state(float* __restrict__ out, int layer) {
    int i = blockIdx.x * blockDim.x + threadIdx.x;
    if (i < Hn * Bn) {
        int j = i >> 5, b = i & 31;
        size_t ybase = (size_t)Tn * Bn * Hn;
        out[ybase + (size_t)layer * Bn * Hn + (size_t)b * Hn + j] = g_hT[i];
        out[ybase + (size_t)2 * Bn * Hn + (size_t)layer * Bn * Hn + (size_t)b * Hn + j] = g_c0[i];
    }
}

// ----------------------------- final y transpose [T][H][B] -> [T][B][H] ----
__global__ __launch_bounds__(256)
void transpose_y(float* __restrict__ out) {
    __shared__ float s[64][33];
    const int t  = blockIdx.x;
    const int j0 = blockIdx.y * 64;
    for (int i = threadIdx.x; i < 64 * 32; i += 256) {
        int jj = i >> 5, b = i & 31;
        s[jj][b] = g_y1T[((size_t)t * Hn + j0 + jj) * Bn + b];
    }
    __syncthreads();
    for (int i = threadIdx.x; i < 64 * 32; i += 256) {
        int b = i >> 6, jj = i & 63;
        out[((size_t)t * Bn + b) * Hn + j0 + jj] = s[jj][b];
    }
}

// ----------------------------- persistent recurrent kernel -----------------
// 148 CTAs x 256 threads, 1 CTA/SM. CTA r owns columns j = r + 148*lc (lc<nloc).
// Warp wp covers k-slice [wp*128, wp*128+128). All 7 weight matrices in smem.
__global__ __launch_bounds__(256, 1)
void lstm_layer(const float* __restrict__ Whh, const float* __restrict__ Wpi,
                const float* __restrict__ Wpf, const float* __restrict__ Wpo,
                int isLayer1)
{
    extern __shared__ __align__(16) float smem[];
    float* sw   = smem;                   // [7 mats][7 cols][1024] = 200704 B
    float* accb = smem + 7 * NC * Hn;     // [8][7][4][32]          =  28672 B

    const int r     = blockIdx.x;
    const int tid   = threadIdx.x;
    const int lane  = tid & 31;
    const int wp    = tid >> 5;
    const int kbase = wp * 128;
    const int nloc  = (r <= 135) ? 7 : 6;
    const int jown  = r + wp * NCTA;      // column this warp finalizes (if wp < nloc)
    float* yT = isLayer1 ? g_y1T : g_y0T;

    // ---- stage step-invariant weights into smem (once) ----
    for (int idx = tid; idx < NC * Hn; idx += 256) {
        int lc = idx >> 10, k = idx & (Hn - 1);
        int j = r + lc * NCTA;
        if (j < Hn) {
            sw[(0 * NC + lc) * Hn + k] = Whh[(size_t)j * Hn + k];
            sw[(1 * NC + lc) * Hn + k] = Whh[(size_t)(Hn + j) * Hn + k];
            sw[(2 * NC + lc) * Hn + k] = Whh[(size_t)(2 * Hn + j) * Hn + k];
            sw[(3 * NC + lc) * Hn + k] = Whh[(size_t)(3 * Hn + j) * Hn + k];
            sw[(4 * NC + lc) * Hn + k] = Wpi[(size_t)j * Hn + k];
            sw[(5 * NC + lc) * Hn + k] = Wpf[(size_t)j * Hn + k];
            sw[(6 * NC + lc) * Hn + k] = Wpo[(size_t)j * Hn + k];
        } else {
            #pragma unroll
            for (int m = 0; m < 7; m++) sw[(m * NC + lc) * Hn + k] = 0.f;
        }
    }
    __syncthreads();

    float cn_reg = 0.f, opart = 0.f;

    for (int t = 0; t < Tn; t++) {
        const float* cread  = (t & 1) ? g_c1 : g_c0;
        float*       cwrite = (t & 1) ? g_c0 : g_c1;
        const float* xg = g_xgT + (size_t)t * G4n * Bn;

        // early independent loads for the finalize step (hide full L2 latency)
        float xgi = 0.f, xgf = 0.f, xgg = 0.f, xgo = 0.f, coldv = 0.f;
        if (wp < nloc) {
            const size_t xb = (size_t)jown * Bn + lane;
            xgi = __ldg(&xg[xb]);
            xgf = __ldg(&xg[(size_t)Hn * Bn + xb]);
            xgg = __ldg(&xg[(size_t)2 * Hn * Bn + xb]);
            xgo = __ldg(&xg[(size_t)3 * Hn * Bn + xb]);
            coldv = __ldcg(&cread[jown * Bn + lane]);
        }

        // ===== phase 1: i, f, g gates + o-partial over this warp's k-slice =====
        ull ai[NC], af[NC], ag[NC], ao[NC];
        #pragma unroll
        for (int lc = 0; lc < NC; lc++) { ai[lc] = 0; af[lc] = 0; ag[lc] = 0; ao[lc] = 0; }

        ull sh2[2][8], sc2[2][8];
        {   // preload chunk 0
            const int k0 = kbase;
            #pragma unroll
            for (int u = 0; u < 8; u++) {
                sh2[0][u] = pack2(__ldcg(&g_hT [(k0 + 2 * u) * Bn + lane]),
                                  __ldcg(&g_hT [(k0 + 2 * u + 1) * Bn + lane]));
                sc2[0][u] = pack2(__ldcg(&cread[(k0 + 2 * u) * Bn + lane]),
                                  __ldcg(&cread[(k0 + 2 * u + 1) * Bn + lane]));
            }
        }
        #pragma unroll 2
        for (int cc = 0; cc < 8; cc++) {
            const int cur = cc & 1, nxt = cur ^ 1;
            if (cc < 7) {   // prefetch next chunk before computing current
                const int k1 = kbase + (cc + 1) * 16;
                #pragma unroll
                for (int u = 0; u < 8; u++) {
                    sh2[nxt][u] = pack2(__ldcg(&g_hT [(k1 + 2 * u) * Bn + lane]),
                                        __ldcg(&g_hT [(k1 + 2 * u + 1) * Bn + lane]));
                    sc2[nxt][u] = pack2(__ldcg(&cread[(k1 + 2 * u) * Bn + lane]),
                                        __ldcg(&cread[(k1 + 2 * u + 1) * Bn + lane]));
                }
            }
            const int k0 = kbase + cc * 16;
            #pragma unroll
            for (int lc = 0; lc < NC; lc++) {
                const ulonglong2* pwi = reinterpret_cast<const ulonglong2*>(sw + (0 * NC + lc) * Hn + k0);
                const ulonglong2* pwf = reinterpret_cast<const ulonglong2*>(sw + (1 * NC + lc) * Hn + k0);
                const ulonglong2* pwg = reinterpret_cast<const ulonglong2*>(sw + (2 * NC + lc) * Hn + k0);
                const ulonglong2* pwo = reinterpret_cast<const ulonglong2*>(sw + (3 * NC + lc) * Hn + k0);
                const ulonglong2* ppi = reinterpret_cast<const ulonglong2*>(sw + (4 * NC + lc) * Hn + k0);
                const ulonglong2* ppf = reinterpret_cast<const ulonglong2*>(sw + (5 * NC + lc) * Hn + k0);
                #pragma unroll
                for (int u = 0; u < 4; u++) {
                    ulonglong2 wi = pwi[u], wf = pwf[u], wg = pwg[u], wo = pwo[u];
                    ulonglong2 vi = ppi[u], vf = ppf[u];
                    ai[lc] = ffma2(wi.x, sh2[cur][2 * u],     ai[lc]);
                    ai[lc] = ffma2(wi.y, sh2[cur][2 * u + 1], ai[lc]);
                    ai[lc] = ffma2(vi.x, sc2[cur][2 * u],     ai[lc]);
                    ai[lc] = ffma2(vi.y, sc2[cur][2 * u + 1], ai[lc]);
                    af[lc] = ffma2(wf.x, sh2[cur][2 * u],     af[lc]);
                    af[lc] = ffma2(wf.y, sh2[cur][2 * u + 1], af[lc]);
                    af[lc] = ffma2(vf.x, sc2[cur][2 * u],     af[lc]);
                    af[lc] = ffma2(vf.y, sc2[cur][2 * u + 1], af[lc]);
                    ag[lc] = ffma2(wg.x, sh2[cur][2 * u],     ag[lc]);
                    ag[lc] = ffma2(wg.y, sh2[cur][2 * u + 1], ag[lc]);
                    ao[lc] = ffma2(wo.x, sh2[cur][2 * u],     ao[lc]);
                    ao[lc] = ffma2(wo.y, sh2[cur][2 * u + 1], ao[lc]);
                }
            }
        }
        #pragma unroll
        for (int lc = 0; lc < NC; lc++) {
            accb[((wp * NC + lc) * 4 + 0) * 32 + lane] = hsum2(ai[lc]);
            accb[((wp * NC + lc) * 4 + 1) * 32 + lane] = hsum2(af[lc]);
            accb[((wp * NC + lc) * 4 + 2) * 32 + lane] = hsum2(ag[lc]);
            accb[((wp * NC + lc) * 4 + 3) * 32 + lane] = hsum2(ao[lc]);
        }
        __syncthreads();

        if (wp < nloc) {
            float si = xgi, sf = xgf, sg = xgg, so = xgo;
            #pragma unroll
            for (int w = 0; w < 8; w++) {
                si += accb[((w * NC + wp) * 4 + 0) * 32 + lane];
                sf += accb[((w * NC + wp) * 4 + 1) * 32 + lane];
                sg += accb[((w * NC + wp) * 4 + 2) * 32 + lane];
                so += accb[((w * NC + wp) * 4 + 3) * 32 + lane];
            }
            float ig = 1.f / (1.f + __expf(-si));
            float fg = 1.f / (1.f + __expf(-sf));
            float gg = tanhf(sg);
            cn_reg = fg * coldv + ig * gg;
            opart  = so;                                // no sigmoid on o (per ref)
            __stcg(&cwrite[jown * Bn + lane], cn_reg);
        }
        grid_barrier(NCTA);

        // ===== phase 2: o += c_new @ Wpo^T (Wpo from smem), then h_new =====
        ull aco[NC];
        #pragma unroll
        for (int lc = 0; lc < NC; lc++) aco[lc] = 0;
        {
            const int k0 = kbase;
            #pragma unroll
            for (int u = 0; u < 8; u++)
                sc2[0][u] = pack2(__ldcg(&cwrite[(k0 + 2 * u) * Bn + lane]),
                                  __ldcg(&cwrite[(k0 + 2 * u + 1) * Bn + lane]));
        }
        #pragma unroll 2
        for (int cc = 0; cc < 8; cc++) {
            const int cur = cc & 1, nxt = cur ^ 1;
            if (cc < 7) {
                const int k1 = kbase + (cc + 1) * 16;
                #pragma unroll
                for (int u = 0; u < 8; u++)
                    sc2[nxt][u] = pack2(__ldcg(&cwrite[(k1 + 2 * u) * Bn + lane]),
                                        __ldcg(&cwrite[(k1 + 2 * u + 1) * Bn + lane]));
            }
            const int k0 = kbase + cc * 16;
            #pragma unroll
            for (int lc = 0; lc < NC; lc++) {
                const ulonglong2* pw = reinterpret_cast<const ulonglong2*>(sw + (6 * NC + lc) * Hn + k0);
                #pragma unroll
                for (int u = 0; u < 4; u++) {
                    ulonglong2 w = pw[u];
                    aco[lc] = ffma2(w.x, sc2[cur][2 * u],     aco[lc]);
                    aco[lc] = ffma2(w.y, sc2[cur][2 * u + 1], aco[lc]);
                }
            }
        }
        #pragma unroll
        for (int lc = 0; lc < NC; lc++)
            accb[((wp * NC + lc) * 4 + 0) * 32 + lane] = hsum2(aco[lc]);
        __syncthreads();

        if (wp < nloc) {
            float so = opart;
            #pragma unroll
            for (int w = 0; w < 8; w++)
                so += accb[((w * NC + wp) * 4 + 0) * 32 + lane];
            float hnew = so * tanhf(cn_reg);
            __stcg(&g_hT[jown * Bn + lane], hnew);
            __stcg(&yT[((size_t)t * Hn + jown) * Bn + lane], hnew);  // coalesced
        }
        grid_barrier(NCTA);
    }
}

// ----------------------------- launch --------------------------------------
extern "C" void kernel_launch(void* const* d_in, const int* in_sizes, int n_in,
                              void* d_out, int out_size) {
    (void)in_sizes; (void)n_in; (void)out_size;
    const float* x    = (const float*)d_in[0];
    const float* wih0 = (const float*)d_in[1];
    const float* whh0 = (const float*)d_in[2];
    const float* wpi0 = (const float*)d_in[3];
    const float* wpf0 = (const float*)d_in[4];
    const float* wpo0 = (const float*)d_in[5];
    const float* wih1 = (const float*)d_in[6];
    const float* whh1 = (const float*)d_in[7];
    const float* wpi1 = (const float*)d_in[8];
    const float* wpf1 = (const float*)d_in[9];
    const float* wpo1 = (const float*)d_in[10];
    float* out = (float*)d_out;

    const int LSTM_SMEM = (7 * NC * Hn + 8 * NC * 4 * 32) * 4;   // 229376 B
    cudaFuncSetAttribute(lstm_layer, cudaFuncAttributeMaxDynamicSharedMemorySize, LSTM_SMEM);

    dim3 gg(Tn * Bn / 128, G4n / 64);   // (128, 64)

    // layer 0
    gemm_xproj<<<gg, 256>>>(x, wih0, 0);
    zero_state<<<128, 256>>>();
    lstm_layer<<<NCTA, 256, LSTM_SMEM>>>(whh0, wpi0, wpf0, wpo0, 0);
    copy_state<<<128, 256>>>(out, 0);

    // layer 1
    gemm_xproj<<<gg, 256>>>(nullptr, wih1, 1);
    zero_state<<<128, 256>>>();
    lstm_layer<<<NCTA, 256, LSTM_SMEM>>>(whh1, wpi1, wpf1, wpo1, 1);
    copy_state<<<128, 256>>>(out, 1);

    // y1 [T][H][B] -> out [T][B][H]
    transpose_y<<<dim3(Tn, Hn / 64), 256>>>(out);
}